// round 5
// baseline (speedup 1.0000x reference)
#include <cuda_runtime.h>
#include <cstdint>
#include <math.h>
#include <mma.h>

using namespace nvcuda;

#define BATCH 512
#define HEADS 4
#define SDIM  256
#define PPIX  196
#define DH    64
#define PD    (PPIX * DH)
#define NPAD  208
#define NCOLS (BATCH * PPIX)    // 100352 = 784 * 128

// ---------------- scratch ----------------
#define QKV_ELEMS (BATCH * HEADS * PPIX * DH)
__device__ float g_q[QKV_ELEMS];
__device__ float g_k[QKV_ELEMS];
__device__ float g_v[QKV_ELEMS];
__device__ float g_av[BATCH * PPIX * SDIM];

__device__ __forceinline__ float f2tf(float v) {
    uint32_t u;
    asm("cvt.rna.tf32.f32 %0, %1;" : "=r"(u) : "f"(v));
    return __uint_as_float(u);
}

typedef wmma::fragment<wmma::matrix_a, 16, 16, 8, wmma::precision::tf32, wmma::row_major> FragA;
typedef wmma::fragment<wmma::matrix_b, 16, 16, 8, wmma::precision::tf32, wmma::row_major> FragBR;
typedef wmma::fragment<wmma::matrix_b, 16, 16, 8, wmma::precision::tf32, wmma::col_major> FragBC;
typedef wmma::fragment<wmma::accumulator, 16, 16, 8, float> FragC;

// smem layout (floats) for projection kernels: two stages of A + B, reused as C
// sA stage: 128 x 36 = 4608   sB stage: 32 x 132 = 4224
#define SA0 0
#define SA1 4608
#define SB0 9216
#define SB1 13440
#define PROJ_SMEM_FLOATS 17664           // 70,656 bytes
#define LDA 36
#define LDB 132
#define LDC 132

// ============================================================================
// Kernel 1: QKV projection as one global GEMM per weight.
// D[o, g] = W[o,:]·x[b,:,p] + bias[o],  g = b*196+p.  CTA: 128(M) x 128(N).
// grid = (784, 6): blockIdx.y = ws*2 + mtile. Reg-staged double buffering.
// ============================================================================
__global__ void __launch_bounds__(256, 2)
qkv_tc(const float* __restrict__ x,
       const float* __restrict__ wq, const float* __restrict__ bq,
       const float* __restrict__ wk, const float* __restrict__ bk,
       const float* __restrict__ wv, const float* __restrict__ bv)
{
    extern __shared__ float sm[];
    const int tid = threadIdx.x;
    const int w   = tid >> 5;
    const int n0  = blockIdx.x * 128;
    const int ws  = blockIdx.y >> 1;
    const int m0  = (blockIdx.y & 1) * 128;

    const float* W    = (ws == 0) ? wq : (ws == 1) ? wk : wv;
    const float* bias = (ws == 0) ? bq : (ws == 1) ? bk : bv;
    float* Og         = (ws == 0) ? g_q : (ws == 1) ? g_k : g_v;

    // B column mapping (computed once)
    const int j     = tid & 127;
    const int chalf = tid >> 7;                 // k rows [0,16) or [16,32)
    const int g     = n0 + j;
    const int bcol  = g / PPIX;
    const int pcol  = g - bcol * PPIX;
    const float* xcol = x + (size_t)bcol * (SDIM * PPIX) + pcol;

    const int wm = (w >> 1) * 32;
    const int wn = (w & 1) * 64;

    FragC acc[2][4];
    #pragma unroll
    for (int i = 0; i < 2; i++)
        #pragma unroll
        for (int q = 0; q < 4; q++) wmma::fill_fragment(acc[i][q], 0.f);

    float ra[16], rb[16];

    // ---- load chunk 0 ----
    #pragma unroll
    for (int t = 0; t < 4; t++) {
        int idx = tid + t * 256;
        int m = idx >> 3, kq = (idx & 7) * 4;
        float4 v = *(const float4*)(W + (size_t)(m0 + m) * SDIM + kq);
        ra[t*4+0] = v.x; ra[t*4+1] = v.y; ra[t*4+2] = v.z; ra[t*4+3] = v.w;
    }
    #pragma unroll
    for (int c = 0; c < 16; c++)
        rb[c] = xcol[(size_t)(chalf * 16 + c) * PPIX];

    // store to stage 0
    #pragma unroll
    for (int t = 0; t < 4; t++) {
        int idx = tid + t * 256;
        int m = idx >> 3, kq = (idx & 7) * 4;
        float4 v = make_float4(f2tf(ra[t*4+0]), f2tf(ra[t*4+1]),
                               f2tf(ra[t*4+2]), f2tf(ra[t*4+3]));
        *(float4*)(sm + SA0 + m * LDA + kq) = v;
    }
    #pragma unroll
    for (int c = 0; c < 16; c++)
        sm[SB0 + (chalf * 16 + c) * LDB + j] = f2tf(rb[c]);
    __syncthreads();

    #pragma unroll
    for (int ch = 0; ch < 8; ch++) {
        const int cur = ch & 1;
        if (ch < 7) {
            const int k0 = (ch + 1) * 32;
            #pragma unroll
            for (int t = 0; t < 4; t++) {
                int idx = tid + t * 256;
                int m = idx >> 3, kq = (idx & 7) * 4;
                float4 v = *(const float4*)(W + (size_t)(m0 + m) * SDIM + k0 + kq);
                ra[t*4+0] = v.x; ra[t*4+1] = v.y; ra[t*4+2] = v.z; ra[t*4+3] = v.w;
            }
            #pragma unroll
            for (int c = 0; c < 16; c++)
                rb[c] = xcol[(size_t)(k0 + chalf * 16 + c) * PPIX];
        }

        const float* cA = sm + (cur ? SA1 : SA0);
        const float* cB = sm + (cur ? SB1 : SB0);
        #pragma unroll
        for (int kk = 0; kk < 32; kk += 8) {
            FragA a0, a1;
            wmma::load_matrix_sync(a0, cA + wm * LDA + kk, LDA);
            wmma::load_matrix_sync(a1, cA + (wm + 16) * LDA + kk, LDA);
            #pragma unroll
            for (int q = 0; q < 4; q++) {
                FragBR bf;
                wmma::load_matrix_sync(bf, cB + kk * LDB + wn + q * 16, LDB);
                wmma::mma_sync(acc[0][q], a0, bf, acc[0][q]);
                wmma::mma_sync(acc[1][q], a1, bf, acc[1][q]);
            }
        }

        if (ch < 7) {
            float* nA = sm + (cur ? SA0 : SA1);
            float* nB = sm + (cur ? SB0 : SB1);
            #pragma unroll
            for (int t = 0; t < 4; t++) {
                int idx = tid + t * 256;
                int m = idx >> 3, kq = (idx & 7) * 4;
                float4 v = make_float4(f2tf(ra[t*4+0]), f2tf(ra[t*4+1]),
                                       f2tf(ra[t*4+2]), f2tf(ra[t*4+3]));
                *(float4*)(nA + m * LDA + kq) = v;
            }
            #pragma unroll
            for (int c = 0; c < 16; c++)
                nB[(chalf * 16 + c) * LDB + j] = f2tf(rb[c]);
        }
        __syncthreads();
    }

    // epilogue: sC = sm (reuse), ld 132
    float* sC = sm;
    #pragma unroll
    for (int i = 0; i < 2; i++)
        #pragma unroll
        for (int q = 0; q < 4; q++)
            wmma::store_matrix_sync(sC + (wm + i * 16) * LDC + wn + q * 16,
                                    acc[i][q], LDC, wmma::mem_row_major);
    __syncthreads();

    // write: column jj (one per 2 threads), half selects head row block
    const int jj   = tid >> 1;
    const int half = tid & 1;
    const int gg   = n0 + jj;
    const int bb   = gg / PPIX;
    const int pp   = gg - bb * PPIX;
    const int h    = (m0 >> 6) + half;
    const float* col = sC + half * 64 * LDC + jj;
    float* ob = Og + (((size_t)bb * HEADS + h) * PPIX + pp) * DH;
    const float* bptr = bias + m0 + half * 64;
    #pragma unroll
    for (int i = 0; i < 16; i++) {
        float4 v;
        v.x = col[(i*4+0) * LDC] + bptr[i*4+0];
        v.y = col[(i*4+1) * LDC] + bptr[i*4+1];
        v.z = col[(i*4+2) * LDC] + bptr[i*4+2];
        v.w = col[(i*4+3) * LDC] + bptr[i*4+3];
        *(float4*)(ob + i * 4) = v;
    }
}

// ============================================================================
// Kernel 2: attention per (b, h, qtile). Last tile (q0=192) is M=16.
// ============================================================================
__global__ void __launch_bounds__(512)
attn_tc()
{
    extern __shared__ float sm[];
    float* sQ   = sm;                    // 64*72 (Q, later AV partial kh=0)
    float* sC2  = sQ + 64 * 72;          // 64*72 (AV partial kh=1)
    float* sKV  = sC2 + 64 * 72;         // 208*72
    float* sS   = sKV + 208 * 72;        // 64*216
    float* sSum = sS + 64 * 216;         // 64

    const int tid = threadIdx.x;
    const int w   = tid >> 5;
    const int b  = blockIdx.z;
    const int h  = blockIdx.y;
    const int q0 = blockIdx.x * 64;
    const int mrows = (q0 == 192) ? 16 : 64;   // valid (padded) query rows

    const size_t bh = (size_t)b * HEADS + h;
    const float* Qg = g_q + bh * PD;
    const float* Kg = g_k + bh * PD;
    const float* Vg = g_v + bh * PD;

    for (int idx = tid; idx < 64 * 16; idx += 512) {
        int r = idx >> 4, c4 = (idx & 15) * 4;
        int gq = q0 + r;
        float4 v = make_float4(0.f, 0.f, 0.f, 0.f);
        if (gq < PPIX) v = *(const float4*)(Qg + (size_t)gq * DH + c4);
        float* dst = sQ + r * 72 + c4;
        dst[0] = f2tf(v.x * 0.125f); dst[1] = f2tf(v.y * 0.125f);
        dst[2] = f2tf(v.z * 0.125f); dst[3] = f2tf(v.w * 0.125f);
    }
    for (int idx = tid; idx < NPAD * 16; idx += 512) {
        int r = idx >> 4, c4 = (idx & 15) * 4;
        float4 v = make_float4(0.f, 0.f, 0.f, 0.f);
        if (r < PPIX) v = *(const float4*)(Kg + (size_t)r * DH + c4);
        float* dst = sKV + r * 72 + c4;
        dst[0] = f2tf(v.x); dst[1] = f2tf(v.y); dst[2] = f2tf(v.z); dst[3] = f2tf(v.w);
    }
    __syncthreads();

    // phase A: S = Q K^T
    {
        const int wm = (w >> 2) * 16;
        if (wm < mrows) {
            const int g  = w & 3;
            const int cnt   = (g == 0) ? 4 : 3;
            const int jbase = (g == 0) ? 0 : (3 * g + 1);
            FragC acc[4];
            #pragma unroll
            for (int q = 0; q < 4; q++) wmma::fill_fragment(acc[q], 0.f);
            #pragma unroll
            for (int kk = 0; kk < 64; kk += 8) {
                FragA a;
                wmma::load_matrix_sync(a, sQ + wm * 72 + kk, 72);
                for (int q = 0; q < cnt; q++) {
                    FragBC bf;
                    wmma::load_matrix_sync(bf, sKV + (jbase + q) * 16 * 72 + kk, 72);
                    wmma::mma_sync(acc[q], a, bf, acc[q]);
                }
            }
            for (int q = 0; q < cnt; q++)
                wmma::store_matrix_sync(sS + wm * 216 + (jbase + q) * 16, acc[q], 216,
                                        wmma::mem_row_major);
        }
    }
    __syncthreads();

    // softmax
    {
        int row = tid >> 3, jl = tid & 7;
        if (row < mrows) {
            float* srow = sS + row * 216;
            float m = -1e30f;
            for (int c = jl; c < PPIX; c += 8) m = fmaxf(m, srow[c]);
            m = fmaxf(m, __shfl_xor_sync(0xffffffffu, m, 1));
            m = fmaxf(m, __shfl_xor_sync(0xffffffffu, m, 2));
            m = fmaxf(m, __shfl_xor_sync(0xffffffffu, m, 4));
            float s = 0.f;
            for (int c = jl; c < NPAD; c += 8) {
                float e = (c < PPIX) ? f2tf(expf(srow[c] - m)) : 0.f;
                srow[c] = e;
                s += e;
            }
            s += __shfl_xor_sync(0xffffffffu, s, 1);
            s += __shfl_xor_sync(0xffffffffu, s, 2);
            s += __shfl_xor_sync(0xffffffffu, s, 4);
            if (jl == 0) sSum[row] = s;
        }
    }
    __syncthreads();

    // fill V
    for (int idx = tid; idx < NPAD * 16; idx += 512) {
        int r = idx >> 4, c4 = (idx & 15) * 4;
        float4 v = make_float4(0.f, 0.f, 0.f, 0.f);
        if (r < PPIX) v = *(const float4*)(Vg + (size_t)r * DH + c4);
        float* dst = sKV + r * 72 + c4;
        dst[0] = f2tf(v.x); dst[1] = f2tf(v.y); dst[2] = f2tf(v.z); dst[3] = f2tf(v.w);
    }
    __syncthreads();

    // phase C: AV = P V, K split 2 x 104
    {
        const int kh = w >> 3;
        const int r2 = w & 7;
        const int wm = (r2 >> 1) * 16;
        if (wm < mrows) {
            const int wn = (r2 & 1) * 32;
            FragC acc[2];
            wmma::fill_fragment(acc[0], 0.f);
            wmma::fill_fragment(acc[1], 0.f);
            #pragma unroll
            for (int s = 0; s < 13; s++) {
                int k = kh * 104 + s * 8;
                FragA a;
                wmma::load_matrix_sync(a, sS + wm * 216 + k, 216);
                FragBR b0, b1;
                wmma::load_matrix_sync(b0, sKV + k * 72 + wn, 72);
                wmma::load_matrix_sync(b1, sKV + k * 72 + wn + 16, 72);
                wmma::mma_sync(acc[0], a, b0, acc[0]);
                wmma::mma_sync(acc[1], a, b1, acc[1]);
            }
            float* buf = kh ? sC2 : sQ;
            wmma::store_matrix_sync(buf + wm * 72 + wn,      acc[0], 72, wmma::mem_row_major);
            wmma::store_matrix_sync(buf + wm * 72 + wn + 16, acc[1], 72, wmma::mem_row_major);
        }
    }
    __syncthreads();

    float* avb = g_av + (size_t)b * (PPIX * SDIM);
    const int d = tid & 63;
    #pragma unroll
    for (int r = 0; r < 8; r++) {
        int q = (tid >> 6) + r * 8;
        int gq = q0 + q;
        if (gq < PPIX) {
            float inv = 1.f / sSum[q];
            avb[(size_t)h * PD + (size_t)gq * DH + d] =
                (sQ[q * 72 + d] + sC2[q * 72 + d]) * inv;
        }
    }
}

// ============================================================================
// Kernel 3: output projection as one global GEMM. grid = (784, 2).
// out[b, o, p] = bo[o] + sum_c wo[o,c] * g_av[b][p][c]
// ============================================================================
__global__ void __launch_bounds__(256, 2)
outproj_tc(const float* __restrict__ wo, const float* __restrict__ bo,
           float* __restrict__ out)
{
    extern __shared__ float sm[];
    const int tid = threadIdx.x;
    const int w   = tid >> 5;
    const int n0  = blockIdx.x * 128;
    const int m0  = blockIdx.y * 128;

    const int j     = tid & 127;
    const int chalf = tid >> 7;
    const int g     = n0 + j;
    const int bcol  = g / PPIX;
    const int pcol  = g - bcol * PPIX;
    const float* avcol = g_av + (size_t)bcol * (PPIX * SDIM) + (size_t)pcol * SDIM
                       + chalf * 16;

    const int wm = (w >> 1) * 32;
    const int wn = (w & 1) * 64;

    FragC acc[2][4];
    #pragma unroll
    for (int i = 0; i < 2; i++)
        #pragma unroll
        for (int q = 0; q < 4; q++) wmma::fill_fragment(acc[i][q], 0.f);

    float ra[16], rb[16];

    #pragma unroll
    for (int t = 0; t < 4; t++) {
        int idx = tid + t * 256;
        int m = idx >> 3, kq = (idx & 7) * 4;
        float4 v = *(const float4*)(wo + (size_t)(m0 + m) * SDIM + kq);
        ra[t*4+0] = v.x; ra[t*4+1] = v.y; ra[t*4+2] = v.z; ra[t*4+3] = v.w;
    }
    #pragma unroll
    for (int t = 0; t < 4; t++) {
        float4 v = *(const float4*)(avcol + t * 4);
        rb[t*4+0] = v.x; rb[t*4+1] = v.y; rb[t*4+2] = v.z; rb[t*4+3] = v.w;
    }
    #pragma unroll
    for (int t = 0; t < 4; t++) {
        int idx = tid + t * 256;
        int m = idx >> 3, kq = (idx & 7) * 4;
        float4 v = make_float4(f2tf(ra[t*4+0]), f2tf(ra[t*4+1]),
                               f2tf(ra[t*4+2]), f2tf(ra[t*4+3]));
        *(float4*)(sm + SA0 + m * LDA + kq) = v;
    }
    #pragma unroll
    for (int c = 0; c < 16; c++)
        sm[SB0 + (chalf * 16 + c) * LDB + j] = f2tf(rb[c]);
    __syncthreads();

    #pragma unroll
    for (int ch = 0; ch < 8; ch++) {
        const int cur = ch & 1;
        if (ch < 7) {
            const int k0 = (ch + 1) * 32;
            #pragma unroll
            for (int t = 0; t < 4; t++) {
                int idx = tid + t * 256;
                int m = idx >> 3, kq = (idx & 7) * 4;
                float4 v = *(const float4*)(wo + (size_t)(m0 + m) * SDIM + k0 + kq);
                ra[t*4+0] = v.x; ra[t*4+1] = v.y; ra[t*4+2] = v.z; ra[t*4+3] = v.w;
            }
            #pragma unroll
            for (int t = 0; t < 4; t++) {
                float4 v = *(const float4*)(avcol + k0 + t * 4);
                rb[t*4+0] = v.x; rb[t*4+1] = v.y; rb[t*4+2] = v.z; rb[t*4+3] = v.w;
            }
        }

        const float* cA = sm + (cur ? SA1 : SA0);
        const float* cB = sm + (cur ? SB1 : SB0);
        #pragma unroll
        for (int kk = 0; kk < 32; kk += 8) {
            FragA a0, a1;
            wmma::load_matrix_sync(a0, cA + wm * LDA + kk, LDA);
            wmma::load_matrix_sync(a1, cA + (wm + 16) * LDA + kk, LDA);
            #pragma unroll
            for (int q = 0; q < 4; q++) {
                FragBR bf;
                wmma::load_matrix_sync(bf, cB + kk * LDB + wn + q * 16, LDB);
                wmma::mma_sync(acc[0][q], a0, bf, acc[0][q]);
                wmma::mma_sync(acc[1][q], a1, bf, acc[1][q]);
            }
        }

        if (ch < 7) {
            float* nA = sm + (cur ? SA0 : SA1);
            float* nB = sm + (cur ? SB0 : SB1);
            #pragma unroll
            for (int t = 0; t < 4; t++) {
                int idx = tid + t * 256;
                int m = idx >> 3, kq = (idx & 7) * 4;
                float4 v = make_float4(f2tf(ra[t*4+0]), f2tf(ra[t*4+1]),
                                       f2tf(ra[t*4+2]), f2tf(ra[t*4+3]));
                *(float4*)(nA + m * LDA + kq) = v;
            }
            #pragma unroll
            for (int c = 0; c < 16; c++)
                nB[(chalf * 16 + c) * LDB + j] = f2tf(rb[c]);
        }
        __syncthreads();
    }

    float* sC = sm;
    #pragma unroll
    for (int i = 0; i < 2; i++)
        #pragma unroll
        for (int q = 0; q < 4; q++)
            wmma::store_matrix_sync(sC + (wm + i * 16) * LDC + wn + q * 16,
                                    acc[i][q], LDC, wmma::mem_row_major);
    __syncthreads();

    // epilogue: thread = column (coalesced over p), loops over 64 m rows
    const int mhalf = tid >> 7;           // rows [0,64) or [64,128)
    float* obase = out + ((size_t)bcol * SDIM + m0 + mhalf * 64) * PPIX + pcol;
    const float* cC = sC + mhalf * 64 * LDC + j;
    const float* bptr = bo + m0 + mhalf * 64;
    #pragma unroll
    for (int m = 0; m < 64; m++)
        obase[(size_t)m * PPIX] = cC[m * LDC] + bptr[m];
}

// ============================================================================
extern "C" void kernel_launch(void* const* d_in, const int* in_sizes, int n_in,
                              void* d_out, int out_size)
{
    const float* x  = (const float*)d_in[0];
    const float* wq = (const float*)d_in[1];
    const float* bq = (const float*)d_in[2];
    const float* wk = (const float*)d_in[3];
    const float* bk = (const float*)d_in[4];
    const float* wv = (const float*)d_in[5];
    const float* bv = (const float*)d_in[6];
    const float* wo = (const float*)d_in[7];
    const float* bo = (const float*)d_in[8];
    float* out = (float*)d_out;

    const int proj_smem = PROJ_SMEM_FLOATS * 4;   // 70,656
    cudaFuncSetAttribute(qkv_tc, cudaFuncAttributeMaxDynamicSharedMemorySize, proj_smem);
    cudaFuncSetAttribute(outproj_tc, cudaFuncAttributeMaxDynamicSharedMemorySize, proj_smem);

    qkv_tc<<<dim3(NCOLS / 128, 6), 256, proj_smem>>>(x, wq, bq, wk, bk, wv, bv);

    const int attn_smem = (64 * 72 * 2 + NPAD * 72 + 64 * 216 + 64) * sizeof(float);
    cudaFuncSetAttribute(attn_tc, cudaFuncAttributeMaxDynamicSharedMemorySize, attn_smem);
    attn_tc<<<dim3(4, HEADS, BATCH), 512, attn_smem>>>();

    outproj_tc<<<dim3(NCOLS / 128, 2), 256, proj_smem>>>(wo, bo, out);
}

// round 6
// speedup vs baseline: 1.3761x; 1.3761x over previous
#include <cuda_runtime.h>
#include <cstdint>
#include <math.h>
#include <mma.h>

using namespace nvcuda;

#define BATCH 512
#define HEADS 4
#define SDIM  256
#define PPIX  196
#define DH    64
#define PD    (PPIX * DH)
#define NPAD  208

// ---------------- scratch ----------------
#define QKV_ELEMS (BATCH * HEADS * PPIX * DH)
__device__ float g_q[QKV_ELEMS];
__device__ float g_k[QKV_ELEMS];
__device__ float g_v[QKV_ELEMS];
__device__ float g_av[BATCH * PPIX * SDIM];

__device__ __forceinline__ float f2tf(float v) {
    uint32_t u;
    asm("cvt.rna.tf32.f32 %0, %1;" : "=r"(u) : "f"(v));
    return __uint_as_float(u);
}

// cp.async helpers
__device__ __forceinline__ void cpa16(float* dst, const float* src) {
    uint32_t d = (uint32_t)__cvta_generic_to_shared(dst);
    asm volatile("cp.async.ca.shared.global [%0], [%1], 16;" :: "r"(d), "l"(src) : "memory");
}
__device__ __forceinline__ void cpg16z(float* dst, const float* src, int bytes) {
    uint32_t d = (uint32_t)__cvta_generic_to_shared(dst);
    asm volatile("cp.async.cg.shared.global [%0], [%1], 16, %2;"
                 :: "r"(d), "l"(src), "r"(bytes) : "memory");
}
#define CP_COMMIT() asm volatile("cp.async.commit_group;" ::: "memory")
#define CP_WAIT(n)  asm volatile("cp.async.wait_group %0;" :: "n"(n) : "memory")

typedef wmma::fragment<wmma::matrix_a, 16, 16, 8, wmma::precision::tf32, wmma::row_major> FragA;
typedef wmma::fragment<wmma::matrix_b, 16, 16, 8, wmma::precision::tf32, wmma::row_major> FragBR;
typedef wmma::fragment<wmma::matrix_b, 16, 16, 8, wmma::precision::tf32, wmma::col_major> FragBC;
typedef wmma::fragment<wmma::accumulator, 16, 16, 8, float> FragC;

template <class F>
__device__ __forceinline__ void frag_cvt(F& f) {
    #pragma unroll
    for (int i = 0; i < f.num_elements; i++) f.x[i] = f2tf(f.x[i]);
}

// ============================================================================
// Kernel 1: QKV projection. CTA 128(M=o) x 64(N=p), warp tile 32x32.
// cp.async double-buffered K chunks of 32; tf32 cvt on fragments.
// grid = (8 = 4 ntile + 4*mtile(2), 3, BATCH)
// stage layout (floats): A 128x36 = 4608, B 32x72 = 2304  -> stage 6912
// ============================================================================
#define QST 6912

__global__ void __launch_bounds__(256)
qkv_tc(const float* __restrict__ x,
       const float* __restrict__ wq, const float* __restrict__ bq,
       const float* __restrict__ wk, const float* __restrict__ bk,
       const float* __restrict__ wv, const float* __restrict__ bv)
{
    extern __shared__ float sm[];
    const int tid = threadIdx.x;
    const int w   = tid >> 5;
    const int n0 = (blockIdx.x & 3) * 64;
    const int m0 = (blockIdx.x >> 2) * 128;
    const int ws = blockIdx.y;
    const int b  = blockIdx.z;

    const float* W    = (ws == 0) ? wq : (ws == 1) ? wk : wv;
    const float* bias = (ws == 0) ? bq : (ws == 1) ? bk : bv;
    float* Og         = (ws == 0) ? g_q : (ws == 1) ? g_k : g_v;

    const float* xb = x + (size_t)b * SDIM * PPIX;
    const int wm = (w >> 1) * 32;
    const int wn = (w & 1) * 32;

    FragC acc[2][2];
    #pragma unroll
    for (int i = 0; i < 2; i++)
        #pragma unroll
        for (int j = 0; j < 2; j++) wmma::fill_fragment(acc[i][j], 0.f);

    // ---- issue chunk (stage s, k offset k0) ----
    #define QKV_ISSUE(s, k0) do {                                                  \
        float* A_ = sm + (s) * QST;                                                \
        float* B_ = A_ + 4608;                                                     \
        _Pragma("unroll")                                                          \
        for (int t = 0; t < 4; t++) {                                              \
            int idx = tid + t * 256;                                               \
            int r = idx >> 3, c = (idx & 7) * 4;                                   \
            cpa16(A_ + r * 36 + c, W + (size_t)(m0 + r) * SDIM + (k0) + c);        \
        }                                                                          \
        _Pragma("unroll")                                                          \
        for (int t = 0; t < 2; t++) {                                              \
            int idx = tid + t * 256;                                               \
            int r = idx >> 4, c = (idx & 15) * 4;                                  \
            int p = n0 + c;                                                        \
            int vb = (PPIX - p) * 4; vb = vb < 0 ? 0 : (vb > 16 ? 16 : vb);        \
            int ps = p < PPIX ? p : 0;                                             \
            cpg16z(B_ + r * 72 + c, xb + (size_t)((k0) + r) * PPIX + ps, vb);      \
        }                                                                          \
        CP_COMMIT();                                                               \
    } while (0)

    QKV_ISSUE(0, 0);

    #pragma unroll
    for (int ch = 0; ch < 8; ch++) {
        CP_WAIT(0);
        __syncthreads();
        if (ch < 7) QKV_ISSUE((ch + 1) & 1, (ch + 1) * 32);

        const float* cA = sm + (ch & 1) * QST;
        const float* cB = cA + 4608;
        #pragma unroll
        for (int kk = 0; kk < 32; kk += 8) {
            FragA a0, a1;
            wmma::load_matrix_sync(a0, cA + wm * 36 + kk, 36);
            wmma::load_matrix_sync(a1, cA + (wm + 16) * 36 + kk, 36);
            frag_cvt(a0); frag_cvt(a1);
            FragBR b0, b1;
            wmma::load_matrix_sync(b0, cB + kk * 72 + wn, 72);
            wmma::load_matrix_sync(b1, cB + kk * 72 + wn + 16, 72);
            frag_cvt(b0); frag_cvt(b1);
            wmma::mma_sync(acc[0][0], a0, b0, acc[0][0]);
            wmma::mma_sync(acc[0][1], a0, b1, acc[0][1]);
            wmma::mma_sync(acc[1][0], a1, b0, acc[1][0]);
            wmma::mma_sync(acc[1][1], a1, b1, acc[1][1]);
        }
    }
    __syncthreads();

    // epilogue: sC reuse (ld 68)
    float* sC = sm;
    #pragma unroll
    for (int i = 0; i < 2; i++)
        #pragma unroll
        for (int j = 0; j < 2; j++)
            wmma::store_matrix_sync(sC + (wm + i * 16) * 68 + wn + j * 16,
                                    acc[i][j], 68, wmma::mem_row_major);
    __syncthreads();

    const int m = tid & 127;
    const int half = tid >> 7;
    const int o = m0 + m;
    const int h = o >> 6, d = o & 63;
    const float bb = bias[o];
    float* ob = Og + (((size_t)b * HEADS + h) * PPIX) * DH + d;
    #pragma unroll
    for (int i = 0; i < 32; i++) {
        int pl = half * 32 + i;
        int p = n0 + pl;
        if (p < PPIX) ob[(size_t)p * DH] = sC[m * 68 + pl] + bb;
    }
}

// ============================================================================
// Kernel 2: attention per (b, h, qtile). V prefetched via cp.async during
// QK^T + softmax. K/V raw fp32 in smem, cvt on fragments. Last tile M=16.
// smem floats: Q 4608 | C2 4608 | K 14976 | V 14976 | S 13824 | sum 64
// ============================================================================
#define AT_Q   0
#define AT_C2  4608
#define AT_K   9216
#define AT_V   24192
#define AT_S   39168
#define AT_SUM 52992
#define AT_TOTAL 53056

__global__ void __launch_bounds__(512)
attn_tc()
{
    extern __shared__ float sm[];
    const int tid = threadIdx.x;
    const int w   = tid >> 5;
    const int b  = blockIdx.z;
    const int h  = blockIdx.y;
    const int q0 = blockIdx.x * 64;
    const int mrows = (q0 == 192) ? 16 : 64;

    const size_t bh = (size_t)b * HEADS + h;
    const float* Qg = g_q + bh * PD;
    const float* Kg = g_k + bh * PD;
    const float* Vg = g_v + bh * PD;

    // issue K group (raw fp32, zero-fill rows >= 196)
    for (int idx = tid; idx < NPAD * 16; idx += 512) {
        int r = idx >> 4, c = (idx & 15) * 4;
        int rs = r < PPIX ? r : 0;
        cpg16z(sm + AT_K + r * 72 + c, Kg + (size_t)rs * DH + c, r < PPIX ? 16 : 0);
    }
    CP_COMMIT();
    // issue V group
    for (int idx = tid; idx < NPAD * 16; idx += 512) {
        int r = idx >> 4, c = (idx & 15) * 4;
        int rs = r < PPIX ? r : 0;
        cpg16z(sm + AT_V + r * 72 + c, Vg + (size_t)rs * DH + c, r < PPIX ? 16 : 0);
    }
    CP_COMMIT();

    // Q fill (scaled, tf32)
    for (int idx = tid; idx < 64 * 16; idx += 512) {
        int r = idx >> 4, c4 = (idx & 15) * 4;
        int gq = q0 + r;
        float4 v = make_float4(0.f, 0.f, 0.f, 0.f);
        if (gq < PPIX) v = *(const float4*)(Qg + (size_t)gq * DH + c4);
        float* dst = sm + AT_Q + r * 72 + c4;
        dst[0] = f2tf(v.x * 0.125f); dst[1] = f2tf(v.y * 0.125f);
        dst[2] = f2tf(v.z * 0.125f); dst[3] = f2tf(v.w * 0.125f);
    }

    CP_WAIT(1);           // K landed (V may still be in flight)
    __syncthreads();

    // ---- phase A: S = Q K^T ----
    {
        const int wm = (w >> 2) * 16;
        if (wm < mrows) {
            const int g  = w & 3;
            const int cnt   = (g == 0) ? 4 : 3;
            const int jbase = (g == 0) ? 0 : (3 * g + 1);
            FragC acc[4];
            #pragma unroll
            for (int q = 0; q < 4; q++) wmma::fill_fragment(acc[q], 0.f);
            #pragma unroll
            for (int kk = 0; kk < 64; kk += 8) {
                FragA a;
                wmma::load_matrix_sync(a, sm + AT_Q + wm * 72 + kk, 72);
                for (int q = 0; q < cnt; q++) {
                    FragBC bf;
                    wmma::load_matrix_sync(bf, sm + AT_K + (jbase + q) * 16 * 72 + kk, 72);
                    frag_cvt(bf);
                    wmma::mma_sync(acc[q], a, bf, acc[q]);
                }
            }
            for (int q = 0; q < cnt; q++)
                wmma::store_matrix_sync(sm + AT_S + wm * 216 + (jbase + q) * 16,
                                        acc[q], 216, wmma::mem_row_major);
        }
    }
    __syncthreads();

    // ---- softmax ----
    {
        int row = tid >> 3, jl = tid & 7;
        if (row < mrows) {
            float* srow = sm + AT_S + row * 216;
            float m = -1e30f;
            for (int c = jl; c < PPIX; c += 8) m = fmaxf(m, srow[c]);
            m = fmaxf(m, __shfl_xor_sync(0xffffffffu, m, 1));
            m = fmaxf(m, __shfl_xor_sync(0xffffffffu, m, 2));
            m = fmaxf(m, __shfl_xor_sync(0xffffffffu, m, 4));
            float s = 0.f;
            for (int c = jl; c < NPAD; c += 8) {
                float e = (c < PPIX) ? f2tf(expf(srow[c] - m)) : 0.f;
                srow[c] = e;
                s += e;
            }
            s += __shfl_xor_sync(0xffffffffu, s, 1);
            s += __shfl_xor_sync(0xffffffffu, s, 2);
            s += __shfl_xor_sync(0xffffffffu, s, 4);
            if (jl == 0) sm[AT_SUM + row] = s;
        }
    }
    CP_WAIT(0);           // V landed
    __syncthreads();

    // ---- phase C: AV = P V, K split 2 x 104 ----
    {
        const int kh = w >> 3;
        const int r2 = w & 7;
        const int wm = (r2 >> 1) * 16;
        if (wm < mrows) {
            const int wn = (r2 & 1) * 32;
            FragC acc[2];
            wmma::fill_fragment(acc[0], 0.f);
            wmma::fill_fragment(acc[1], 0.f);
            #pragma unroll
            for (int s = 0; s < 13; s++) {
                int k = kh * 104 + s * 8;
                FragA a;
                wmma::load_matrix_sync(a, sm + AT_S + wm * 216 + k, 216);
                FragBR b0, b1;
                wmma::load_matrix_sync(b0, sm + AT_V + k * 72 + wn, 72);
                wmma::load_matrix_sync(b1, sm + AT_V + k * 72 + wn + 16, 72);
                frag_cvt(b0); frag_cvt(b1);
                wmma::mma_sync(acc[0], a, b0, acc[0]);
                wmma::mma_sync(acc[1], a, b1, acc[1]);
            }
            float* buf = sm + (kh ? AT_C2 : AT_Q);
            wmma::store_matrix_sync(buf + wm * 72 + wn,      acc[0], 72, wmma::mem_row_major);
            wmma::store_matrix_sync(buf + wm * 72 + wn + 16, acc[1], 72, wmma::mem_row_major);
        }
    }
    __syncthreads();

    float* avb = g_av + (size_t)b * (PPIX * SDIM);
    const int d = tid & 63;
    #pragma unroll
    for (int r = 0; r < 8; r++) {
        int q = (tid >> 6) + r * 8;
        int gq = q0 + q;
        if (gq < PPIX) {
            float inv = 1.f / sm[AT_SUM + q];
            avb[(size_t)h * PD + (size_t)gq * DH + d] =
                (sm[AT_Q + q * 72 + d] + sm[AT_C2 + q * 72 + d]) * inv;
        }
    }
}

// ============================================================================
// Kernel 3: output projection. CTA 128(M=o) x 64(N=p), warp 32x32, cp.async.
// stage (floats): A 128x36 = 4608, B 64x40 = 2560 -> stage 7168
// ============================================================================
#define OST 7168

__global__ void __launch_bounds__(256)
outproj_tc(const float* __restrict__ wo, const float* __restrict__ bo,
           float* __restrict__ out)
{
    extern __shared__ float sm[];
    const int tid = threadIdx.x;
    const int w   = tid >> 5;
    const int n0 = (blockIdx.x & 3) * 64;
    const int m0 = (blockIdx.x >> 2) * 128;
    const int b  = blockIdx.y;

    const float* avb = g_av + (size_t)b * (PPIX * SDIM);
    const int wm = (w >> 1) * 32;
    const int wn = (w & 1) * 32;

    FragC acc[2][2];
    #pragma unroll
    for (int i = 0; i < 2; i++)
        #pragma unroll
        for (int j = 0; j < 2; j++) wmma::fill_fragment(acc[i][j], 0.f);

    #define OUT_ISSUE(s, k0) do {                                                  \
        float* A_ = sm + (s) * OST;                                                \
        float* B_ = A_ + 4608;                                                     \
        _Pragma("unroll")                                                          \
        for (int t = 0; t < 4; t++) {                                              \
            int idx = tid + t * 256;                                               \
            int r = idx >> 3, c = (idx & 7) * 4;                                   \
            cpa16(A_ + r * 36 + c, wo + (size_t)(m0 + r) * SDIM + (k0) + c);       \
        }                                                                          \
        _Pragma("unroll")                                                          \
        for (int t = 0; t < 2; t++) {                                              \
            int idx = tid + t * 256;                                               \
            int r = idx >> 3, c = (idx & 7) * 4;                                   \
            int p = n0 + r;                                                        \
            int ps = p < PPIX ? p : 0;                                             \
            cpg16z(B_ + r * 40 + c, avb + (size_t)ps * SDIM + (k0) + c,            \
                   p < PPIX ? 16 : 0);                                             \
        }                                                                          \
        CP_COMMIT();                                                               \
    } while (0)

    OUT_ISSUE(0, 0);

    #pragma unroll
    for (int ch = 0; ch < 8; ch++) {
        CP_WAIT(0);
        __syncthreads();
        if (ch < 7) OUT_ISSUE((ch + 1) & 1, (ch + 1) * 32);

        const float* cA = sm + (ch & 1) * OST;
        const float* cB = cA + 4608;
        #pragma unroll
        for (int kk = 0; kk < 32; kk += 8) {
            FragA a0, a1;
            wmma::load_matrix_sync(a0, cA + wm * 36 + kk, 36);
            wmma::load_matrix_sync(a1, cA + (wm + 16) * 36 + kk, 36);
            frag_cvt(a0); frag_cvt(a1);
            FragBC b0, b1;
            wmma::load_matrix_sync(b0, cB + wn * 40 + kk, 40);
            wmma::load_matrix_sync(b1, cB + (wn + 16) * 40 + kk, 40);
            frag_cvt(b0); frag_cvt(b1);
            wmma::mma_sync(acc[0][0], a0, b0, acc[0][0]);
            wmma::mma_sync(acc[0][1], a0, b1, acc[0][1]);
            wmma::mma_sync(acc[1][0], a1, b0, acc[1][0]);
            wmma::mma_sync(acc[1][1], a1, b1, acc[1][1]);
        }
    }
    __syncthreads();

    float* sC = sm;
    #pragma unroll
    for (int i = 0; i < 2; i++)
        #pragma unroll
        for (int j = 0; j < 2; j++)
            wmma::store_matrix_sync(sC + (wm + i * 16) * 68 + wn + j * 16,
                                    acc[i][j], 68, wmma::mem_row_major);
    __syncthreads();

    const int m = tid >> 1;
    const int half = tid & 1;
    const int o = m0 + m;
    const float bb = bo[o];
    float* orow = out + ((size_t)b * SDIM + o) * PPIX;
    if (n0 + 63 < PPIX) {
        #pragma unroll
        for (int i = 0; i < 8; i++) {
            int pl = half * 32 + i * 4;
            float4 v;
            v.x = sC[m * 68 + pl + 0] + bb;
            v.y = sC[m * 68 + pl + 1] + bb;
            v.z = sC[m * 68 + pl + 2] + bb;
            v.w = sC[m * 68 + pl + 3] + bb;
            *(float4*)(orow + n0 + pl) = v;
        }
    } else {
        #pragma unroll
        for (int i = 0; i < 32; i++) {
            int pl = half * 32 + i;
            int p = n0 + pl;
            if (p < PPIX) orow[p] = sC[m * 68 + pl] + bb;
        }
    }
}

// ============================================================================
extern "C" void kernel_launch(void* const* d_in, const int* in_sizes, int n_in,
                              void* d_out, int out_size)
{
    const float* x  = (const float*)d_in[0];
    const float* wq = (const float*)d_in[1];
    const float* bq = (const float*)d_in[2];
    const float* wk = (const float*)d_in[3];
    const float* bk = (const float*)d_in[4];
    const float* wv = (const float*)d_in[5];
    const float* bv = (const float*)d_in[6];
    const float* wo = (const float*)d_in[7];
    const float* bo = (const float*)d_in[8];
    float* out = (float*)d_out;

    const int qkv_smem = 2 * QST * 4;           // 55,296
    cudaFuncSetAttribute(qkv_tc, cudaFuncAttributeMaxDynamicSharedMemorySize, qkv_smem);
    qkv_tc<<<dim3(8, 3, BATCH), 256, qkv_smem>>>(x, wq, bq, wk, bk, wv, bv);

    const int attn_smem = AT_TOTAL * 4;         // 212,224
    cudaFuncSetAttribute(attn_tc, cudaFuncAttributeMaxDynamicSharedMemorySize, attn_smem);
    attn_tc<<<dim3(4, HEADS, BATCH), 512, attn_smem>>>();

    const int out_smem = 2 * OST * 4;           // 57,344
    cudaFuncSetAttribute(outproj_tc, cudaFuncAttributeMaxDynamicSharedMemorySize, out_smem);
    outproj_tc<<<dim3(8, BATCH), 256, out_smem>>>(wo, bo, out);
}

// round 7
// speedup vs baseline: 1.7993x; 1.3076x over previous
#include <cuda_runtime.h>
#include <cstdint>
#include <math.h>
#include <mma.h>

using namespace nvcuda;

#define BATCH 512
#define HEADS 4
#define SDIM  256
#define PPIX  196
#define DH    64
#define PD    (PPIX * DH)
#define NPAD  208

// ---------------- scratch ----------------
#define QKV_ELEMS (BATCH * HEADS * PPIX * DH)
__device__ float g_q[QKV_ELEMS];
__device__ float g_k[QKV_ELEMS];
__device__ float g_v[QKV_ELEMS];
__device__ float g_av[BATCH * PPIX * SDIM];

__device__ __forceinline__ float f2tf(float v) {
    uint32_t u;
    asm("cvt.rna.tf32.f32 %0, %1;" : "=r"(u) : "f"(v));
    return __uint_as_float(u);
}

__device__ __forceinline__ void cpg16z(float* dst, const float* src, int bytes) {
    uint32_t d = (uint32_t)__cvta_generic_to_shared(dst);
    asm volatile("cp.async.cg.shared.global [%0], [%1], 16, %2;"
                 :: "r"(d), "l"(src), "r"(bytes) : "memory");
}
#define CP_COMMIT() asm volatile("cp.async.commit_group;" ::: "memory")
#define CP_WAIT(n)  asm volatile("cp.async.wait_group %0;" :: "n"(n) : "memory")

typedef wmma::fragment<wmma::matrix_a, 16, 16, 8, wmma::precision::tf32, wmma::row_major> FragA;
typedef wmma::fragment<wmma::matrix_b, 16, 16, 8, wmma::precision::tf32, wmma::row_major> FragBR;
typedef wmma::fragment<wmma::matrix_b, 16, 16, 8, wmma::precision::tf32, wmma::col_major> FragBC;
typedef wmma::fragment<wmma::accumulator, 16, 16, 8, float> FragC;

template <class F>
__device__ __forceinline__ void frag_cvt(F& f) {
    #pragma unroll
    for (int i = 0; i < f.num_elements; i++) f.x[i] = f2tf(f.x[i]);
}

// ============================================================================
// Kernel 1: QKV projection. CTA 128(M=o) x 64(N=p), warp 32x32.
// Register-staged double-buffered K chunks of 32, tf32 cvt at smem store.
// stage (floats): A 128x36 = 4608 | B 32x72 = 2304 -> 6912; two stages.
// grid = (8, 3, BATCH)
// ============================================================================
#define QST 6912

__global__ void __launch_bounds__(256, 2)
qkv_tc(const float* __restrict__ x,
       const float* __restrict__ wq, const float* __restrict__ bq,
       const float* __restrict__ wk, const float* __restrict__ bk,
       const float* __restrict__ wv, const float* __restrict__ bv)
{
    extern __shared__ float sm[];
    const int tid = threadIdx.x;
    const int w   = tid >> 5;
    const int n0 = (blockIdx.x & 3) * 64;
    const int m0 = (blockIdx.x >> 2) * 128;
    const int ws = blockIdx.y;
    const int b  = blockIdx.z;

    const float* W    = (ws == 0) ? wq : (ws == 1) ? wk : wv;
    const float* bias = (ws == 0) ? bq : (ws == 1) ? bk : bv;
    float* Og         = (ws == 0) ? g_q : (ws == 1) ? g_k : g_v;

    const float* xb = x + (size_t)b * SDIM * PPIX;
    const int wm = (w >> 1) * 32;
    const int wn = (w & 1) * 32;

    // A-fill indices: 128x32 over 4 passes; B-fill: 32x64 over 2 passes
    const int ar = tid >> 3,  ac = (tid & 7) * 4;     // + 32 rows per pass
    const int br = tid >> 4,  bc = (tid & 15) * 4;    // + 16 rows per pass
    const int bp = n0 + bc;
    const bool bvalid = (bp <= 192);                  // full float4 valid

    FragC acc[2][2];
    #pragma unroll
    for (int i = 0; i < 2; i++)
        #pragma unroll
        for (int j = 0; j < 2; j++) wmma::fill_fragment(acc[i][j], 0.f);

    float ra[16], rb[8];

    #define QKV_LOAD(k0) do {                                                     \
        _Pragma("unroll")                                                         \
        for (int t = 0; t < 4; t++) {                                             \
            float4 v = *(const float4*)(W + (size_t)(m0 + ar + t * 32) * SDIM     \
                                          + (k0) + ac);                           \
            ra[t*4+0]=v.x; ra[t*4+1]=v.y; ra[t*4+2]=v.z; ra[t*4+3]=v.w;           \
        }                                                                         \
        _Pragma("unroll")                                                         \
        for (int t = 0; t < 2; t++) {                                             \
            float4 v = make_float4(0.f,0.f,0.f,0.f);                              \
            if (bvalid) v = *(const float4*)(xb + (size_t)((k0) + br + t * 16)    \
                                               * PPIX + bp);                      \
            rb[t*4+0]=v.x; rb[t*4+1]=v.y; rb[t*4+2]=v.z; rb[t*4+3]=v.w;           \
        }                                                                         \
    } while (0)

    #define QKV_STORE(s) do {                                                    \
        float* A_ = sm + (s) * QST;                                               \
        float* B_ = A_ + 4608;                                                    \
        _Pragma("unroll")                                                         \
        for (int t = 0; t < 4; t++) {                                             \
            float4 v = make_float4(f2tf(ra[t*4+0]), f2tf(ra[t*4+1]),              \
                                   f2tf(ra[t*4+2]), f2tf(ra[t*4+3]));             \
            *(float4*)(A_ + (ar + t * 32) * 36 + ac) = v;                         \
        }                                                                         \
        _Pragma("unroll")                                                         \
        for (int t = 0; t < 2; t++) {                                             \
            float4 v = make_float4(f2tf(rb[t*4+0]), f2tf(rb[t*4+1]),              \
                                   f2tf(rb[t*4+2]), f2tf(rb[t*4+3]));             \
            *(float4*)(B_ + (br + t * 16) * 72 + bc) = v;                         \
        }                                                                         \
    } while (0)

    QKV_LOAD(0);
    QKV_STORE(0);
    __syncthreads();

    #pragma unroll
    for (int ch = 0; ch < 8; ch++) {
        if (ch < 7) QKV_LOAD((ch + 1) * 32);

        const float* cA = sm + (ch & 1) * QST;
        const float* cB = cA + 4608;
        #pragma unroll
        for (int kk = 0; kk < 32; kk += 8) {
            FragA a0, a1;
            wmma::load_matrix_sync(a0, cA + wm * 36 + kk, 36);
            wmma::load_matrix_sync(a1, cA + (wm + 16) * 36 + kk, 36);
            FragBR b0, b1;
            wmma::load_matrix_sync(b0, cB + kk * 72 + wn, 72);
            wmma::load_matrix_sync(b1, cB + kk * 72 + wn + 16, 72);
            wmma::mma_sync(acc[0][0], a0, b0, acc[0][0]);
            wmma::mma_sync(acc[0][1], a0, b1, acc[0][1]);
            wmma::mma_sync(acc[1][0], a1, b0, acc[1][0]);
            wmma::mma_sync(acc[1][1], a1, b1, acc[1][1]);
        }

        if (ch < 7) QKV_STORE((ch + 1) & 1);
        __syncthreads();
    }

    // epilogue (reuse smem as C, ld 68)
    float* sC = sm;
    #pragma unroll
    for (int i = 0; i < 2; i++)
        #pragma unroll
        for (int j = 0; j < 2; j++)
            wmma::store_matrix_sync(sC + (wm + i * 16) * 68 + wn + j * 16,
                                    acc[i][j], 68, wmma::mem_row_major);
    __syncthreads();

    const int m = tid & 127;
    const int half = tid >> 7;
    const int o = m0 + m;
    const int h = o >> 6, d = o & 63;
    const float bb = bias[o];
    float* ob = Og + (((size_t)b * HEADS + h) * PPIX) * DH + d;
    #pragma unroll
    for (int i = 0; i < 32; i++) {
        int pl = half * 32 + i;
        int p = n0 + pl;
        if (p < PPIX) ob[(size_t)p * DH] = sC[m * 68 + pl] + bb;
    }
}

// ============================================================================
// Kernel 2: attention, 32-row q-tiles, 2 CTAs/SM. grid = (7, HEADS, BATCH).
// smem floats: Q 2304 | S 6912 | KV 14976 | sum 32  = 24224 (96,896 B)
// ============================================================================
#define ATQ   0
#define ATS   2304
#define ATKV  9216
#define ATSUM 24192
#define ATTOT 24224

__global__ void __launch_bounds__(512, 2)
attn_tc()
{
    extern __shared__ float sm[];
    const int tid = threadIdx.x;
    const int w   = tid >> 5;
    const int b  = blockIdx.z;
    const int h  = blockIdx.y;
    const int q0 = blockIdx.x * 32;
    const int mrows = (q0 == 192) ? 16 : 32;

    const size_t bh = (size_t)b * HEADS + h;
    const float* Qg = g_q + bh * PD;
    const float* Kg = g_k + bh * PD;
    const float* Vg = g_v + bh * PD;

    // issue K + Q (raw fp32)
    for (int idx = tid; idx < NPAD * 16; idx += 512) {
        int r = idx >> 4, c = (idx & 15) * 4;
        int rs = r < PPIX ? r : 0;
        cpg16z(sm + ATKV + r * 72 + c, Kg + (size_t)rs * DH + c, r < PPIX ? 16 : 0);
    }
    for (int idx = tid; idx < 32 * 16; idx += 512) {
        int r = idx >> 4, c = (idx & 15) * 4;
        int gq = q0 + r;
        int rs = gq < PPIX ? gq : 0;
        cpg16z(sm + ATQ + r * 72 + c, Qg + (size_t)rs * DH + c, gq < PPIX ? 16 : 0);
    }
    CP_COMMIT();
    CP_WAIT(0);
    __syncthreads();

    // ---- phase A: S = Q K^T (raw scores; scale folded into softmax) ----
    {
        const int wm = (w >> 3) * 16;
        if (wm < mrows) {
            const int g = w & 7;
            const int cnt   = (g < 5) ? 2 : 1;
            const int jbase = (g < 5) ? g * 2 : 5 + g;
            FragC acc[2];
            wmma::fill_fragment(acc[0], 0.f);
            wmma::fill_fragment(acc[1], 0.f);
            #pragma unroll
            for (int kk = 0; kk < 64; kk += 8) {
                FragA a;
                wmma::load_matrix_sync(a, sm + ATQ + wm * 72 + kk, 72);
                frag_cvt(a);
                for (int q = 0; q < cnt; q++) {
                    FragBC bf;
                    wmma::load_matrix_sync(bf, sm + ATKV + (jbase + q) * 16 * 72 + kk, 72);
                    frag_cvt(bf);
                    wmma::mma_sync(acc[q], a, bf, acc[q]);
                }
            }
            for (int q = 0; q < cnt; q++)
                wmma::store_matrix_sync(sm + ATS + wm * 216 + (jbase + q) * 16,
                                        acc[q], 216, wmma::mem_row_major);
        }
    }
    __syncthreads();

    // issue V (overwrites K; K fully consumed) — overlaps softmax
    for (int idx = tid; idx < NPAD * 16; idx += 512) {
        int r = idx >> 4, c = (idx & 15) * 4;
        int rs = r < PPIX ? r : 0;
        cpg16z(sm + ATKV + r * 72 + c, Vg + (size_t)rs * DH + c, r < PPIX ? 16 : 0);
    }
    CP_COMMIT();

    // ---- softmax (16 lanes per row) ----
    {
        int row = tid >> 4, jl = tid & 15;
        if (row < mrows) {
            float* srow = sm + ATS + row * 216;
            float m = -1e30f;
            for (int c = jl; c < PPIX; c += 16) m = fmaxf(m, srow[c]);
            m = fmaxf(m, __shfl_xor_sync(0xffffffffu, m, 1));
            m = fmaxf(m, __shfl_xor_sync(0xffffffffu, m, 2));
            m = fmaxf(m, __shfl_xor_sync(0xffffffffu, m, 4));
            m = fmaxf(m, __shfl_xor_sync(0xffffffffu, m, 8));
            float s = 0.f;
            for (int c = jl; c < NPAD; c += 16) {
                float e = (c < PPIX) ? f2tf(__expf((srow[c] - m) * 0.125f)) : 0.f;
                srow[c] = e;
                s += e;
            }
            s += __shfl_xor_sync(0xffffffffu, s, 1);
            s += __shfl_xor_sync(0xffffffffu, s, 2);
            s += __shfl_xor_sync(0xffffffffu, s, 4);
            s += __shfl_xor_sync(0xffffffffu, s, 8);
            if (jl == 0) sm[ATSUM + row] = s;
        }
    }
    CP_WAIT(0);
    __syncthreads();

    // ---- phase C: AV = P V; 16 warps = 2(wm) x 4(wn16) x 2(K half) ----
    {
        const int kh = w >> 3;
        const int r2 = w & 7;
        const int wm = (r2 >> 2) * 16;
        const int wn = (r2 & 3) * 16;
        const bool act = (wm < mrows);
        FragC acc;
        wmma::fill_fragment(acc, 0.f);
        if (act) {
            #pragma unroll
            for (int s = 0; s < 13; s++) {
                int k = kh * 104 + s * 8;
                FragA a;
                wmma::load_matrix_sync(a, sm + ATS + wm * 216 + k, 216);
                FragBR bf;
                wmma::load_matrix_sync(bf, sm + ATKV + k * 72 + wn, 72);
                frag_cvt(bf);
                wmma::mma_sync(acc, a, bf, acc);
            }
        }
        __syncthreads();   // all V reads done before kh=1 overwrites ATKV head
        if (act) {
            float* buf = sm + (kh ? ATKV : ATQ);
            wmma::store_matrix_sync(buf + wm * 72 + wn, acc, 72, wmma::mem_row_major);
        }
    }
    __syncthreads();

    // epilogue: normalize, write flat av [p][h*64+d]
    float* avb = g_av + (size_t)b * (PPIX * SDIM);
    const int d = tid & 63;
    #pragma unroll
    for (int r = 0; r < 4; r++) {
        int q = (tid >> 6) + r * 8;
        int gq = q0 + q;
        if (gq < PPIX) {
            float inv = 1.f / sm[ATSUM + q];
            avb[(size_t)h * PD + (size_t)gq * DH + d] =
                (sm[ATQ + q * 72 + d] + sm[ATKV + q * 72 + d]) * inv;
        }
    }
}

// ============================================================================
// Kernel 3: output projection. CTA 128x64, warp 32x32, reg-staged dbuf.
// stage (floats): A 128x36 = 4608 | B 64x40 = 2560 -> 7168; two stages.
// grid = (8, BATCH)
// ============================================================================
#define OST 7168

__global__ void __launch_bounds__(256, 2)
outproj_tc(const float* __restrict__ wo, const float* __restrict__ bo,
           float* __restrict__ out)
{
    extern __shared__ float sm[];
    const int tid = threadIdx.x;
    const int w   = tid >> 5;
    const int n0 = (blockIdx.x & 3) * 64;
    const int m0 = (blockIdx.x >> 2) * 128;
    const int b  = blockIdx.y;

    const float* avb = g_av + (size_t)b * (PPIX * SDIM);
    const int wm = (w >> 1) * 32;
    const int wn = (w & 1) * 32;

    const int ar = tid >> 3, ac = (tid & 7) * 4;     // A: +32 rows/pass, 4 passes
    const int br = tid >> 3, bc = (tid & 7) * 4;     // B: +32 rows/pass, 2 passes
    const int bp0 = n0 + br;

    FragC acc[2][2];
    #pragma unroll
    for (int i = 0; i < 2; i++)
        #pragma unroll
        for (int j = 0; j < 2; j++) wmma::fill_fragment(acc[i][j], 0.f);

    float ra[16], rb[8];

    #define OUT_LOAD(k0) do {                                                     \
        _Pragma("unroll")                                                         \
        for (int t = 0; t < 4; t++) {                                             \
            float4 v = *(const float4*)(wo + (size_t)(m0 + ar + t * 32) * SDIM    \
                                           + (k0) + ac);                          \
            ra[t*4+0]=v.x; ra[t*4+1]=v.y; ra[t*4+2]=v.z; ra[t*4+3]=v.w;           \
        }                                                                         \
        _Pragma("unroll")                                                         \
        for (int t = 0; t < 2; t++) {                                             \
            int p = bp0 + t * 32;                                                 \
            float4 v = make_float4(0.f,0.f,0.f,0.f);                              \
            if (p < PPIX) v = *(const float4*)(avb + (size_t)p * SDIM + (k0) + bc);\
            rb[t*4+0]=v.x; rb[t*4+1]=v.y; rb[t*4+2]=v.z; rb[t*4+3]=v.w;           \
        }                                                                         \
    } while (0)

    #define OUT_STORE(s) do {                                                    \
        float* A_ = sm + (s) * OST;                                               \
        float* B_ = A_ + 4608;                                                    \
        _Pragma("unroll")                                                         \
        for (int t = 0; t < 4; t++) {                                             \
            float4 v = make_float4(f2tf(ra[t*4+0]), f2tf(ra[t*4+1]),              \
                                   f2tf(ra[t*4+2]), f2tf(ra[t*4+3]));             \
            *(float4*)(A_ + (ar + t * 32) * 36 + ac) = v;                         \
        }                                                                         \
        _Pragma("unroll")                                                         \
        for (int t = 0; t < 2; t++) {                                             \
            float4 v = make_float4(f2tf(rb[t*4+0]), f2tf(rb[t*4+1]),              \
                                   f2tf(rb[t*4+2]), f2tf(rb[t*4+3]));             \
            *(float4*)(B_ + (br + t * 32) * 40 + bc) = v;                         \
        }                                                                         \
    } while (0)

    OUT_LOAD(0);
    OUT_STORE(0);
    __syncthreads();

    #pragma unroll
    for (int ch = 0; ch < 8; ch++) {
        if (ch < 7) OUT_LOAD((ch + 1) * 32);

        const float* cA = sm + (ch & 1) * OST;
        const float* cB = cA + 4608;
        #pragma unroll
        for (int kk = 0; kk < 32; kk += 8) {
            FragA a0, a1;
            wmma::load_matrix_sync(a0, cA + wm * 36 + kk, 36);
            wmma::load_matrix_sync(a1, cA + (wm + 16) * 36 + kk, 36);
            FragBC b0, b1;
            wmma::load_matrix_sync(b0, cB + wn * 40 + kk, 40);
            wmma::load_matrix_sync(b1, cB + (wn + 16) * 40 + kk, 40);
            wmma::mma_sync(acc[0][0], a0, b0, acc[0][0]);
            wmma::mma_sync(acc[0][1], a0, b1, acc[0][1]);
            wmma::mma_sync(acc[1][0], a1, b0, acc[1][0]);
            wmma::mma_sync(acc[1][1], a1, b1, acc[1][1]);
        }

        if (ch < 7) OUT_STORE((ch + 1) & 1);
        __syncthreads();
    }

    float* sC = sm;
    #pragma unroll
    for (int i = 0; i < 2; i++)
        #pragma unroll
        for (int j = 0; j < 2; j++)
            wmma::store_matrix_sync(sC + (wm + i * 16) * 68 + wn + j * 16,
                                    acc[i][j], 68, wmma::mem_row_major);
    __syncthreads();

    const int m = tid >> 1;
    const int half = tid & 1;
    const int o = m0 + m;
    const float bb = bo[o];
    float* orow = out + ((size_t)b * SDIM + o) * PPIX;
    if (n0 + 63 < PPIX) {
        #pragma unroll
        for (int i = 0; i < 8; i++) {
            int pl = half * 32 + i * 4;
            float4 v;
            v.x = sC[m * 68 + pl + 0] + bb;
            v.y = sC[m * 68 + pl + 1] + bb;
            v.z = sC[m * 68 + pl + 2] + bb;
            v.w = sC[m * 68 + pl + 3] + bb;
            *(float4*)(orow + n0 + pl) = v;
        }
    } else {
        #pragma unroll
        for (int i = 0; i < 32; i++) {
            int pl = half * 32 + i;
            int p = n0 + pl;
            if (p < PPIX) orow[p] = sC[m * 68 + pl] + bb;
        }
    }
}

// ============================================================================
extern "C" void kernel_launch(void* const* d_in, const int* in_sizes, int n_in,
                              void* d_out, int out_size)
{
    const float* x  = (const float*)d_in[0];
    const float* wq = (const float*)d_in[1];
    const float* bq = (const float*)d_in[2];
    const float* wk = (const float*)d_in[3];
    const float* bk = (const float*)d_in[4];
    const float* wv = (const float*)d_in[5];
    const float* bv = (const float*)d_in[6];
    const float* wo = (const float*)d_in[7];
    const float* bo = (const float*)d_in[8];
    float* out = (float*)d_out;

    const int qkv_smem = 2 * QST * 4;           // 55,296
    cudaFuncSetAttribute(qkv_tc, cudaFuncAttributeMaxDynamicSharedMemorySize, qkv_smem);
    qkv_tc<<<dim3(8, 3, BATCH), 256, qkv_smem>>>(x, wq, bq, wk, bk, wv, bv);

    const int attn_smem = ATTOT * 4;            // 96,896
    cudaFuncSetAttribute(attn_tc, cudaFuncAttributeMaxDynamicSharedMemorySize, attn_smem);
    attn_tc<<<dim3(7, HEADS, BATCH), 512, attn_smem>>>();

    const int out_smem = 2 * OST * 4;           // 57,344
    cudaFuncSetAttribute(outproj_tc, cudaFuncAttributeMaxDynamicSharedMemorySize, out_smem);
    outproj_tc<<<dim3(8, BATCH), 256, out_smem>>>(wo, bo, out);
}